// round 8
// baseline (speedup 1.0000x reference)
#include <cuda_runtime.h>
#include <math.h>

#define EPS 1e-12f
constexpr int K    = 8;
constexpr int MAXE = 3200000;    // 2 * E_UND
constexpr int MAXN = 100000;
constexpr int ITERS = 5;         // fixed by problem setup
constexpr int SCAN_TILE = 1024;
constexpr int MAXBLK = 128;      // >= ceil(MAXN/1024) = 98

// Scratch (allocation-free rule: __device__ globals)
__device__ __align__(256) float g_msgA[(size_t)MAXE * K];
__device__ __align__(256) float g_msgB[(size_t)MAXE * K];
__device__ __align__(256) float g_pp[(size_t)MAXN * K];
__device__ int   g_cnt[MAXN];        // histogram, then slot cursor
__device__ int   g_off[MAXN + 1];    // CSR offsets (by dst)
__device__ int   g_bsum[MAXBLK];
__device__ int   g_boff[MAXBLK];
__device__ int   g_nodeof[MAXE];     // slot -> dst node of stored edge
__device__ int   g_wslot[MAXE];      // slot -> slot of reverse edge
__device__ int   g_pos[MAXE];        // edge -> slot
__device__ float g_psi[K * K];

__device__ __forceinline__ void ldg_v8(const float* p, float* v) {
    unsigned r0, r1, r2, r3, r4, r5, r6, r7;
    asm volatile("ld.global.v8.b32 {%0,%1,%2,%3,%4,%5,%6,%7}, [%8];"
                 : "=r"(r0), "=r"(r1), "=r"(r2), "=r"(r3),
                   "=r"(r4), "=r"(r5), "=r"(r6), "=r"(r7)
                 : "l"(p));
    v[0] = __uint_as_float(r0); v[1] = __uint_as_float(r1);
    v[2] = __uint_as_float(r2); v[3] = __uint_as_float(r3);
    v[4] = __uint_as_float(r4); v[5] = __uint_as_float(r5);
    v[6] = __uint_as_float(r6); v[7] = __uint_as_float(r7);
}

// 0: psi = exp(potential) (block 0), zero histogram.
__global__ void k_init(const float* __restrict__ pot, int N) {
    if (blockIdx.x == 0 && threadIdx.x < K * K) g_psi[threadIdx.x] = expf(pot[threadIdx.x]);
    int i = blockIdx.x * blockDim.x + threadIdx.x;
    if (i < N) g_cnt[i] = 0;
}

// 1: histogram of dst.
__global__ void k_hist(const int* __restrict__ dst, int E) {
    int e = blockIdx.x * blockDim.x + threadIdx.x;
    if (e < E) atomicAdd(&g_cnt[dst[e]], 1);
}

// 2: per-block exclusive scan of g_cnt tile -> g_off (block-local), block totals -> g_bsum.
__global__ void k_scanA(int N) {
    __shared__ int s[SCAN_TILE];
    int t = threadIdx.x;
    int i = blockIdx.x * SCAN_TILE + t;
    int v = (i < N) ? g_cnt[i] : 0;
    s[t] = v;
    __syncthreads();
#pragma unroll
    for (int st = 1; st < SCAN_TILE; st <<= 1) {
        int x = (t >= st) ? s[t - st] : 0;
        __syncthreads();
        s[t] += x;
        __syncthreads();
    }
    if (i < N) g_off[i] = s[t] - v;          // block-local exclusive
    if (t == SCAN_TILE - 1) g_bsum[blockIdx.x] = s[t];
}

// 3: scan block sums (single block).
__global__ void k_scanB(int nblk) {
    __shared__ int s[MAXBLK];
    int t = threadIdx.x;
    int v = (t < nblk) ? g_bsum[t] : 0;
    s[t] = v;
    __syncthreads();
#pragma unroll
    for (int st = 1; st < MAXBLK; st <<= 1) {
        int x = (t >= st) ? s[t - st] : 0;
        __syncthreads();
        s[t] += x;
        __syncthreads();
    }
    g_boff[t] = s[t] - v;
}

// 4: finalize offsets + init cursor.
__global__ void k_scanC(int N, int E) {
    int i = blockIdx.x * blockDim.x + threadIdx.x;
    if (i < N) {
        int o = g_off[i] + g_boff[i >> 10];
        g_off[i] = o;
        g_cnt[i] = o;                         // cursor
    }
    if (i == 0) g_off[N] = E;
}

// 5: assign slots; scatter initial messages + nodeof.
__global__ void k_pos(const int* __restrict__ dst, const float* __restrict__ msgs, int E) {
    int e = blockIdx.x * blockDim.x + threadIdx.x;
    if (e >= E) return;
    int d = dst[e];
    int q = atomicAdd(&g_cnt[d], 1);
    g_pos[e] = q;
    g_nodeof[q] = d;
    const float4* m4 = reinterpret_cast<const float4*>(msgs + (size_t)e * K);
    float4 a = m4[0], b = m4[1];
    float4* o = reinterpret_cast<float4*>(g_msgA + (size_t)q * K);
    o[0] = a; o[1] = b;
}

// 6: wslot[pos[e]] = pos[rev(e)], with rev(e) = e +- E/2.
__global__ void k_build(int E, int E2) {
    int e = blockIdx.x * blockDim.x + threadIdx.x;
    if (e >= E) return;
    int re = (e < E2) ? e + E2 : e - E2;
    g_wslot[g_pos[e]] = g_pos[re];
}

// Per-iteration A: warp-per-node aggregation. pp = prior * exp(sum logs of incoming).
__global__ void __launch_bounds__(256)
k_agg(const float* __restrict__ msg, const float* __restrict__ prior,
      float* __restrict__ pp, int N) {
    int w = (blockIdx.x * blockDim.x + threadIdx.x) >> 5;
    int lane = threadIdx.x & 31;
    if (w >= N) return;
    int b0 = g_off[w], b1 = g_off[w + 1];
    float a0 = 0.f, a1 = 0.f, a2 = 0.f, a3 = 0.f, a4 = 0.f, a5 = 0.f, a6 = 0.f, a7 = 0.f;
    for (int q = b0 + lane; q < b1; q += 32) {
        const float4* m4 = reinterpret_cast<const float4*>(msg + (size_t)q * K);
        float4 x = m4[0], y = m4[1];
        a0 += __logf(fmaxf(x.x, EPS)); a1 += __logf(fmaxf(x.y, EPS));
        a2 += __logf(fmaxf(x.z, EPS)); a3 += __logf(fmaxf(x.w, EPS));
        a4 += __logf(fmaxf(y.x, EPS)); a5 += __logf(fmaxf(y.y, EPS));
        a6 += __logf(fmaxf(y.z, EPS)); a7 += __logf(fmaxf(y.w, EPS));
    }
#pragma unroll
    for (int st = 16; st >= 1; st >>= 1) {
        a0 += __shfl_down_sync(0xffffffffu, a0, st);
        a1 += __shfl_down_sync(0xffffffffu, a1, st);
        a2 += __shfl_down_sync(0xffffffffu, a2, st);
        a3 += __shfl_down_sync(0xffffffffu, a3, st);
        a4 += __shfl_down_sync(0xffffffffu, a4, st);
        a5 += __shfl_down_sync(0xffffffffu, a5, st);
        a6 += __shfl_down_sync(0xffffffffu, a6, st);
        a7 += __shfl_down_sync(0xffffffffu, a7, st);
    }
    if (lane == 0) {
        const float4* pr = reinterpret_cast<const float4*>(prior + (size_t)w * K);
        float4 p0 = pr[0], p1 = pr[1];
        float4 o0 = make_float4(p0.x * __expf(a0), p0.y * __expf(a1),
                                p0.z * __expf(a2), p0.w * __expf(a3));
        float4 o1 = make_float4(p1.x * __expf(a4), p1.y * __expf(a5),
                                p1.z * __expf(a6), p1.w * __expf(a7));
        float4* po = reinterpret_cast<float4*>(pp + (size_t)w * K);
        po[0] = o0; po[1] = o1;
    }
}

// Per-iteration B: slot-parallel message update.
// Slot q holds m[j->i] (i = nodeof[q]); produce m_new[i->j] into wslot[q].
__global__ void __launch_bounds__(256)
k_upd(const float* __restrict__ in, float* __restrict__ out,
      const float* __restrict__ pp, int E) {
    __shared__ float sp[K * K];
    if (threadIdx.x < K * K) sp[threadIdx.x] = g_psi[threadIdx.x];
    __syncthreads();

    int q = blockIdx.x * blockDim.x + threadIdx.x;
    if (q >= E) return;
    int i = g_nodeof[q];
    int w = g_wslot[q];

    const float4* m4 = reinterpret_cast<const float4*>(in + (size_t)q * K);
    float4 m0 = m4[0], m1 = m4[1];
    float pa[K];
    ldg_v8(pp + (size_t)i * K, pa);       // broadcast across warp (sorted slots)

    float t[K];
    t[0] = fmaxf(__fdividef(pa[0], fmaxf(m0.x, EPS)), EPS);
    t[1] = fmaxf(__fdividef(pa[1], fmaxf(m0.y, EPS)), EPS);
    t[2] = fmaxf(__fdividef(pa[2], fmaxf(m0.z, EPS)), EPS);
    t[3] = fmaxf(__fdividef(pa[3], fmaxf(m0.w, EPS)), EPS);
    t[4] = fmaxf(__fdividef(pa[4], fmaxf(m1.x, EPS)), EPS);
    t[5] = fmaxf(__fdividef(pa[5], fmaxf(m1.y, EPS)), EPS);
    t[6] = fmaxf(__fdividef(pa[6], fmaxf(m1.z, EPS)), EPS);
    t[7] = fmaxf(__fdividef(pa[7], fmaxf(m1.w, EPS)), EPS);

    float m[K];
#pragma unroll
    for (int k = 0; k < K; k++) m[k] = t[0] * sp[k];
#pragma unroll
    for (int j = 1; j < K; j++) {
#pragma unroll
        for (int k = 0; k < K; k++) m[k] = fmaf(t[j], sp[j * K + k], m[k]);
    }
    float s = (m[0] + m[1]) + (m[2] + m[3]) + ((m[4] + m[5]) + (m[6] + m[7]));
    float inv = __fdividef(1.0f, fmaxf(s, EPS));
#pragma unroll
    for (int k = 0; k < K; k++) m[k] = m[k] * inv;

    float4* o = reinterpret_cast<float4*>(out + (size_t)w * K);
    o[0] = make_float4(m[0], m[1], m[2], m[3]);
    o[1] = make_float4(m[4], m[5], m[6], m[7]);
}

// Final: out = normalize(max(pp, EPS))   (pp = prior * exp(in_log_final))
__global__ void k_belief(const float* __restrict__ pp, float* __restrict__ out, int N) {
    int i = blockIdx.x * blockDim.x + threadIdx.x;
    if (i >= N) return;
    const float4* p4 = reinterpret_cast<const float4*>(pp + (size_t)i * K);
    float4 a = p4[0], b = p4[1];
    float v[K] = { fmaxf(a.x, EPS), fmaxf(a.y, EPS), fmaxf(a.z, EPS), fmaxf(a.w, EPS),
                   fmaxf(b.x, EPS), fmaxf(b.y, EPS), fmaxf(b.z, EPS), fmaxf(b.w, EPS) };
    float s = (v[0] + v[1]) + (v[2] + v[3]) + ((v[4] + v[5]) + (v[6] + v[7]));
    float inv = __fdividef(1.0f, fmaxf(s, EPS));
    float4* o4 = reinterpret_cast<float4*>(out + (size_t)i * K);
    o4[0] = make_float4(v[0] * inv, v[1] * inv, v[2] * inv, v[3] * inv);
    o4[1] = make_float4(v[4] * inv, v[5] * inv, v[6] * inv, v[7] * inv);
}

extern "C" void kernel_launch(void* const* d_in, const int* in_sizes, int n_in,
                              void* d_out, int out_size) {
    const float* prior     = (const float*)d_in[0];
    const float* messages  = (const float*)d_in[1];
    const float* potential = (const float*)d_in[2];
    // d_in[3] = src (unused here)
    const int*   dst       = (const int*)d_in[4];
    // d_in[5] = rev_idx (structural: rev[e] = e +- E/2)
    // d_in[6] = iterations (fixed 5 by problem setup)

    int E  = in_sizes[3];
    int E2 = E / 2;
    int N  = in_sizes[0] / K;
    float* out = (float*)d_out;

    float *msgA, *msgB, *pp;
    cudaGetSymbolAddress((void**)&msgA, g_msgA);
    cudaGetSymbolAddress((void**)&msgB, g_msgB);
    cudaGetSymbolAddress((void**)&pp, g_pp);

    const int TB = 256;
    int gE = (E + TB - 1) / TB;
    int gN = (N + TB - 1) / TB;
    int nblk = (N + SCAN_TILE - 1) / SCAN_TILE;
    int gWarp = (N * 32 + TB - 1) / TB;       // warp-per-node grid

    // Prologue: CSR by dst + initial message scatter into sorted slots.
    k_init<<<gN, TB>>>(potential, N);
    k_hist<<<gE, TB>>>(dst, E);
    k_scanA<<<nblk, SCAN_TILE>>>(N);
    k_scanB<<<1, MAXBLK>>>(nblk);
    k_scanC<<<gN, TB>>>(N, E);
    k_pos<<<gE, TB>>>(dst, messages, E);
    k_build<<<gE, TB>>>(E, E2);

    // Iterations: aggregate (pp) then update (double-buffered messages).
    const float* cur = msgA;
    float* nxt = msgB;
    for (int it = 0; it < ITERS; it++) {
        k_agg<<<gWarp, TB>>>(cur, prior, pp, N);
        k_upd<<<gE, TB>>>(cur, nxt, pp, E);
        const float* t = cur; cur = nxt; nxt = (float*)t;
    }

    // Final aggregation + belief.
    k_agg<<<gWarp, TB>>>(cur, prior, pp, N);
    k_belief<<<gN, TB>>>(pp, out, N);
}

// round 9
// speedup vs baseline: 2.0926x; 2.0926x over previous
#include <cuda_runtime.h>
#include <cuda_fp16.h>
#include <math.h>

#define EPS 1e-12f
constexpr int K      = 8;
constexpr int MAXE   = 3200000;   // 2 * E_UND
constexpr int MAXN   = 100000;
constexpr int ITERS  = 5;         // fixed by problem setup

// Scratch (allocation-free rule: __device__ globals)
// Messages stored fp16: 8 halves = 16B per edge row. Only the divisor path is
// quantized (logs are scattered from fp32 values before the store).
__device__ __align__(256) __half g_msg[(size_t)MAXE * K];
__device__ __align__(256) float  g_inlog[2][(size_t)MAXN * K];
__device__ __align__(256) float  g_pp[(size_t)MAXN * K];
__device__ float g_psi[K * K];

__device__ __forceinline__ void red_add_v4(float* p, float a, float b, float c, float d) {
    asm volatile("red.global.add.v4.f32 [%0], {%1,%2,%3,%4};"
                 :: "l"(p), "f"(a), "f"(b), "f"(c), "f"(d) : "memory");
}

// 256-bit gather for the 32B-aligned, L2-resident pp rows.
__device__ __forceinline__ void ldg_v8(const float* p, float* v) {
    unsigned r0, r1, r2, r3, r4, r5, r6, r7;
    asm volatile("ld.global.v8.b32 {%0,%1,%2,%3,%4,%5,%6,%7}, [%8];"
                 : "=r"(r0), "=r"(r1), "=r"(r2), "=r"(r3),
                   "=r"(r4), "=r"(r5), "=r"(r6), "=r"(r7)
                 : "l"(p));
    v[0] = __uint_as_float(r0); v[1] = __uint_as_float(r1);
    v[2] = __uint_as_float(r2); v[3] = __uint_as_float(r3);
    v[4] = __uint_as_float(r4); v[5] = __uint_as_float(r5);
    v[6] = __uint_as_float(r6); v[7] = __uint_as_float(r7);
}

// Read 8 halves (16B) -> 8 floats.
__device__ __forceinline__ void ldg_h8(const __half* p, float* v) {
    uint4 u = *reinterpret_cast<const uint4*>(p);
    __half2 h0 = *reinterpret_cast<__half2*>(&u.x);
    __half2 h1 = *reinterpret_cast<__half2*>(&u.y);
    __half2 h2 = *reinterpret_cast<__half2*>(&u.z);
    __half2 h3 = *reinterpret_cast<__half2*>(&u.w);
    float2 f0 = __half22float2(h0), f1 = __half22float2(h1);
    float2 f2 = __half22float2(h2), f3 = __half22float2(h3);
    v[0] = f0.x; v[1] = f0.y; v[2] = f1.x; v[3] = f1.y;
    v[4] = f2.x; v[5] = f2.y; v[6] = f3.x; v[7] = f3.y;
}
// Write 8 floats -> 8 halves (16B).
__device__ __forceinline__ void stg_h8(__half* p, const float* v) {
    __half2 h0 = __floats2half2_rn(v[0], v[1]);
    __half2 h1 = __floats2half2_rn(v[2], v[3]);
    __half2 h2 = __floats2half2_rn(v[4], v[5]);
    __half2 h3 = __floats2half2_rn(v[6], v[7]);
    uint4 u;
    u.x = *reinterpret_cast<unsigned*>(&h0);
    u.y = *reinterpret_cast<unsigned*>(&h1);
    u.z = *reinterpret_cast<unsigned*>(&h2);
    u.w = *reinterpret_cast<unsigned*>(&h3);
    *reinterpret_cast<uint4*>(p) = u;
}

// Launch 0: zero inlog[0] AND compute psi = exp(potential) (block 0 only).
__global__ void k_zero_psi(float* __restrict__ p, int n4, const float* __restrict__ pot) {
    if (blockIdx.x == 0 && threadIdx.x < K * K) g_psi[threadIdx.x] = expf(pot[threadIdx.x]);
    int i = blockIdx.x * blockDim.x + threadIdx.x;
    if (i < n4) reinterpret_cast<float4*>(p)[i] = make_float4(0.f, 0.f, 0.f, 0.f);
}

// Launch 1: initial scatter over all E edges (fp32 input messages).
__global__ void k_scatter(const float* __restrict__ msgs, const int* __restrict__ dst,
                          float* __restrict__ inlog, int E) {
    int e = blockIdx.x * blockDim.x + threadIdx.x;
    if (e >= E) return;
    const float4* m4 = reinterpret_cast<const float4*>(msgs + (size_t)e * K);
    float4 a = m4[0], b = m4[1];
    float* d = inlog + (size_t)dst[e] * K;
    red_add_v4(d,     __logf(fmaxf(a.x, EPS)), __logf(fmaxf(a.y, EPS)),
                      __logf(fmaxf(a.z, EPS)), __logf(fmaxf(a.w, EPS)));
    red_add_v4(d + 4, __logf(fmaxf(b.x, EPS)), __logf(fmaxf(b.y, EPS)),
                      __logf(fmaxf(b.z, EPS)), __logf(fmaxf(b.w, EPS)));
}

// Per-node: pp = prior * exp(in_log_cur); zero in_log_next.
__global__ void k_pp_zero(const float* __restrict__ inlog_cur, const float* __restrict__ prior,
                          float* __restrict__ pp, float* __restrict__ inlog_next_zero, int n4) {
    int i = blockIdx.x * blockDim.x + threadIdx.x;
    if (i >= n4) return;
    float4 v = reinterpret_cast<const float4*>(inlog_cur)[i];
    float4 p = reinterpret_cast<const float4*>(prior)[i];
    float4 o;
    o.x = p.x * __expf(v.x); o.y = p.y * __expf(v.y);
    o.z = p.z * __expf(v.z); o.w = p.w * __expf(v.w);
    reinterpret_cast<float4*>(pp)[i] = o;
    reinterpret_cast<float4*>(inlog_next_zero)[i] = make_float4(0.f, 0.f, 0.f, 0.f);
}

// One direction: t = max(pp / max(mdiv,EPS), EPS); m = normalize(t @ psi);
// optionally store m (fp16); scatter log(m) (fp32) into inlog_dest.
template <bool WRITE_MSG>
__device__ __forceinline__ void one_dir(
    const float* __restrict__ sp,
    const float* __restrict__ md,           // divisor (partner's old message, fp32 regs)
    const float* __restrict__ pa,           // pp row (fp32 regs)
    __half* __restrict__ out_slot,
    float* __restrict__ inlog_dest)
{
    float t[K];
#pragma unroll
    for (int k = 0; k < K; k++)
        t[k] = fmaxf(__fdividef(pa[k], fmaxf(md[k], EPS)), EPS);

    float m[K];
#pragma unroll
    for (int k = 0; k < K; k++) m[k] = t[0] * sp[k];
#pragma unroll
    for (int j = 1; j < K; j++) {
#pragma unroll
        for (int k = 0; k < K; k++) m[k] = fmaf(t[j], sp[j * K + k], m[k]);
    }

    float s = (m[0] + m[1]) + (m[2] + m[3]) + ((m[4] + m[5]) + (m[6] + m[7]));
    float inv = __fdividef(1.0f, fmaxf(s, EPS));
#pragma unroll
    for (int k = 0; k < K; k++) m[k] = m[k] * inv;

    if (WRITE_MSG) stg_h8(out_slot, m);

    float l[K];
#pragma unroll
    for (int k = 0; k < K; k++) l[k] = __logf(m[k] > EPS ? m[k] : EPS);
    red_add_v4(inlog_dest,     l[0], l[1], l[2], l[3]);
    red_add_v4(inlog_dest + 4, l[4], l[5], l[6], l[7]);
}

// Pair update, in-place on the fp16 buffer: thread p handles edges p and r=p+E2.
// FIRST=true reads fp32 input messages instead.
template <bool WRITE_MSG, bool FIRST>
__global__ void __launch_bounds__(256, 5)
k_update(const float* __restrict__ cur32, __half* __restrict__ msg16,
         const float* __restrict__ pp, const int* __restrict__ src,
         const int* __restrict__ dst, float* __restrict__ inlog_nxt, int E2) {
    __shared__ float sp[K * K];
    if (threadIdx.x < K * K) sp[threadIdx.x] = g_psi[threadIdx.x];
    __syncthreads();

    int p = blockIdx.x * blockDim.x + threadIdx.x;
    if (p >= E2) return;

    int r  = p + E2;
    int s1 = src[p];
    int s2 = dst[p];              // == src[r]

    float ma[K], mb[K];
    if (FIRST) {
        const float4* a4 = reinterpret_cast<const float4*>(cur32 + (size_t)p * K);
        const float4* b4 = reinterpret_cast<const float4*>(cur32 + (size_t)r * K);
        float4 a0 = a4[0], a1 = a4[1], b0 = b4[0], b1 = b4[1];
        ma[0]=a0.x; ma[1]=a0.y; ma[2]=a0.z; ma[3]=a0.w;
        ma[4]=a1.x; ma[5]=a1.y; ma[6]=a1.z; ma[7]=a1.w;
        mb[0]=b0.x; mb[1]=b0.y; mb[2]=b0.z; mb[3]=b0.w;
        mb[4]=b1.x; mb[5]=b1.y; mb[6]=b1.z; mb[7]=b1.w;
    } else {
        ldg_h8(msg16 + (size_t)p * K, ma);
        ldg_h8(msg16 + (size_t)r * K, mb);
    }
    float pa[K], pb[K];
    ldg_v8(pp + (size_t)s1 * K, pa);
    ldg_v8(pp + (size_t)s2 * K, pb);

    // Direction p: src=s1 -> dst=s2, divisor = old m[r].
    one_dir<WRITE_MSG>(sp, mb, pa, msg16 + (size_t)p * K, inlog_nxt + (size_t)s2 * K);
    // Direction r: src=s2 -> dst=s1, divisor = old m[p].
    one_dir<WRITE_MSG>(sp, ma, pb, msg16 + (size_t)r * K, inlog_nxt + (size_t)s1 * K);
}

// Beliefs: out = normalize( max(prior * exp(in_log), EPS) )
__global__ void k_belief(const float* __restrict__ inlog, const float* __restrict__ prior,
                         float* __restrict__ out, int N) {
    int i = blockIdx.x * blockDim.x + threadIdx.x;
    if (i >= N) return;
    const float4* l4 = reinterpret_cast<const float4*>(inlog + (size_t)i * K);
    const float4* p4 = reinterpret_cast<const float4*>(prior + (size_t)i * K);
    float4 la = l4[0], lb = l4[1];
    float4 pa = p4[0], pb = p4[1];
    float b[K];
    b[0] = fmaxf(pa.x * __expf(la.x), EPS);
    b[1] = fmaxf(pa.y * __expf(la.y), EPS);
    b[2] = fmaxf(pa.z * __expf(la.z), EPS);
    b[3] = fmaxf(pa.w * __expf(la.w), EPS);
    b[4] = fmaxf(pb.x * __expf(lb.x), EPS);
    b[5] = fmaxf(pb.y * __expf(lb.y), EPS);
    b[6] = fmaxf(pb.z * __expf(lb.z), EPS);
    b[7] = fmaxf(pb.w * __expf(lb.w), EPS);
    float s = (b[0] + b[1]) + (b[2] + b[3]) + ((b[4] + b[5]) + (b[6] + b[7]));
    float inv = __fdividef(1.0f, fmaxf(s, EPS));
    float4* o4 = reinterpret_cast<float4*>(out + (size_t)i * K);
    o4[0] = make_float4(b[0] * inv, b[1] * inv, b[2] * inv, b[3] * inv);
    o4[1] = make_float4(b[4] * inv, b[5] * inv, b[6] * inv, b[7] * inv);
}

extern "C" void kernel_launch(void* const* d_in, const int* in_sizes, int n_in,
                              void* d_out, int out_size) {
    const float* prior     = (const float*)d_in[0];
    const float* messages  = (const float*)d_in[1];
    const float* potential = (const float*)d_in[2];
    const int*   src       = (const int*)d_in[3];
    const int*   dst       = (const int*)d_in[4];
    // d_in[5] = rev_idx (structural: rev[p] = p + E/2 for p < E/2)
    // d_in[6] = iterations (fixed 5 by problem setup)

    int E  = in_sizes[3];
    int E2 = E / 2;
    int N  = in_sizes[0] / K;
    float* out = (float*)d_out;

    __half* msg;
    float *inlogBase, *pp;
    cudaGetSymbolAddress((void**)&msg, g_msg);
    cudaGetSymbolAddress((void**)&inlogBase, g_inlog);
    cudaGetSymbolAddress((void**)&pp, g_pp);
    float* inlog[2] = { inlogBase, inlogBase + (size_t)MAXN * K };

    const int TB = 256;
    int gE  = (E + TB - 1) / TB;
    int gE2 = (E2 + TB - 1) / TB;
    int n4  = (N * K) / 4;
    int gN4 = (n4 + TB - 1) / TB;
    int gN  = (N + TB - 1) / TB;

    // Launch order: 0:zero_psi 1:scatter 2:pp 3:upd(it0) 4:pp 5:upd(it1) <- ncu -s 5
    k_zero_psi<<<gN4, TB>>>(inlog[0], n4, potential);
    k_scatter<<<gE, TB>>>(messages, dst, inlog[0], E);

    for (int it = 0; it < ITERS; it++) {
        k_pp_zero<<<gN4, TB>>>(inlog[it & 1], prior, pp, inlog[(it + 1) & 1], n4);
        if (it == 0) {
            k_update<true, true><<<gE2, TB>>>(messages, msg, pp, src, dst,
                                              inlog[1], E2);
        } else if (it + 1 < ITERS) {
            k_update<true, false><<<gE2, TB>>>(nullptr, msg, pp, src, dst,
                                               inlog[(it + 1) & 1], E2);
        } else {
            // Final iteration: messages feed only the inlog scatter; skip store.
            k_update<false, false><<<gE2, TB>>>(nullptr, msg, pp, src, dst,
                                                inlog[(it + 1) & 1], E2);
        }
    }

    k_belief<<<gN, TB>>>(inlog[ITERS & 1], prior, out, N);
}